// round 15
// baseline (speedup 1.0000x reference)
#include <cuda_runtime.h>
#include <cuda_fp16.h>
#include <cstdint>

// Complex attention via portable mma.sync m16n8k16 fp16 (f32 accum).
// Round 15: pair-granular QK->softmax->PV interleave collapses S live range
// (64 -> 16 regs) enabling 3 CTAs/SM. Math/order bit-identical to R13.
#define SLEN 2048
#define PLANE (4*8*2048*64)
#define TEMP_INV 0.125f
#define NT 32
#define SGNH 0x80008000u

// smem uint4 units: K[2][1024] @0, V[2][1024] @2048
#define SMEM_BYTES (4096*16)   // 65536

__device__ uint4 gK[32*32*1024];
__device__ uint4 gV[32*32*1024];

static __device__ __forceinline__ void mma16(float* d, const uint32_t* a,
                                             uint32_t b0, uint32_t b1) {
    asm volatile("mma.sync.aligned.m16n8k16.row.col.f32.f16.f16.f32 "
                 "{%0,%1,%2,%3},{%4,%5,%6,%7},{%8,%9},{%0,%1,%2,%3};"
                 : "+f"(d[0]), "+f"(d[1]), "+f"(d[2]), "+f"(d[3])
                 : "r"(a[0]), "r"(a[1]), "r"(a[2]), "r"(a[3]), "r"(b0), "r"(b1));
}
static __device__ __forceinline__ uint32_t h2u(float x, float y) {
    __half2 h = __floats2half2_rn(x, y);
    return *(uint32_t*)&h;
}
static __device__ __forceinline__ void cp16(void* dst, const uint4* src) {
    unsigned a = (unsigned)__cvta_generic_to_shared(dst);
    asm volatile("cp.async.cg.shared.global [%0], [%1], 16;" :: "r"(a), "l"(src));
}

// x bits: lane[0:5) ktp[5:7) nt[7:10) t[10:15) h[15:20)
__global__ __launch_bounds__(256)
void prep_k(const float* __restrict__ kr, const float* __restrict__ ki) {
    int x = blockIdx.x * 256 + threadIdx.x;
    int lane = x & 31, ktp = (x >> 5) & 3, nt = (x >> 7) & 7;
    int t = (x >> 10) & 31, h = x >> 15;
    int g = lane >> 2, l = lane & 3;
    int row = ((h << 11) + (t << 6) + (nt << 3) + g) << 6;   // *64
    int k0 = (ktp << 4) + 2 * l, k1 = k0 + 8;
    gK[x] = make_uint4(h2u(kr[row + k0], kr[row + k0 + 1]),
                       h2u(kr[row + k1], kr[row + k1 + 1]),
                       h2u(ki[row + k0], ki[row + k0 + 1]),
                       h2u(ki[row + k1], ki[row + k1 + 1]));
}
__global__ __launch_bounds__(256)
void prep_v(const float* __restrict__ vr, const float* __restrict__ vi) {
    int x = blockIdx.x * 256 + threadIdx.x;
    int lane = x & 31, ktp = (x >> 5) & 3, nt = (x >> 7) & 7;
    int t = (x >> 10) & 31, h = x >> 15;
    int g = lane >> 2, l = lane & 3;
    int d = (nt << 3) + g;
    size_t base = ((size_t)h << 17) + d;                     // h*2048*64 + d
    int key0 = ((t << 6) + (ktp << 4) + 2 * l) << 6;         // *64
    int key8 = key0 + (8 << 6);
    gV[x] = make_uint4(h2u(vr[base + key0], vr[base + key0 + 64]),
                       h2u(vr[base + key8], vr[base + key8 + 64]),
                       h2u(vi[base + key0], vi[base + key0 + 64]),
                       h2u(vi[base + key8], vi[base + key8 + 64]));
}

__global__ __launch_bounds__(128, 3)
void cvattn_mma(const float* __restrict__ qr_g, const float* __restrict__ qi_g,
                float* __restrict__ out)
{
    extern __shared__ uint4 smem4[];
    const int tid  = threadIdx.x;
    const int w    = tid >> 5;                 // 0..3
    const int lane = tid & 31;
    const int g    = lane >> 2;
    const int l    = lane & 3;
    const int bh   = blockIdx.y;
    const size_t hoff = (size_t)bh * (SLEN * 64);
    const int m0 = blockIdx.x << 6;            // 64-row query tile

    const uint4* srcK = gK + ((size_t)bh << 15);   // 32 tiles x 1024
    const uint4* srcV = gV + ((size_t)bh << 15);

    // ---- Q fragments in fp16 (rows m0+w*16+g, +8), scaled ----
    uint32_t qa[4][4], qb[4][4];
    {
        const float* Q0r = qr_g + hoff + (size_t)(m0 + w * 16 + g) * 64;
        const float* Q1r = Q0r + 8 * 64;
        const float* Q0i = qi_g + hoff + (size_t)(m0 + w * 16 + g) * 64;
        const float* Q1i = Q0i + 8 * 64;
#pragma unroll
        for (int ktp = 0; ktp < 4; ++ktp) {
            int k0 = ktp * 16 + 2 * l, k1 = k0 + 8;
            qa[ktp][0] = h2u(Q0r[k0] * TEMP_INV, Q0r[k0 + 1] * TEMP_INV);
            qa[ktp][1] = h2u(Q1r[k0] * TEMP_INV, Q1r[k0 + 1] * TEMP_INV);
            qa[ktp][2] = h2u(Q0r[k1] * TEMP_INV, Q0r[k1 + 1] * TEMP_INV);
            qa[ktp][3] = h2u(Q1r[k1] * TEMP_INV, Q1r[k1 + 1] * TEMP_INV);
            qb[ktp][0] = h2u(Q0i[k0] * TEMP_INV, Q0i[k0 + 1] * TEMP_INV);
            qb[ktp][1] = h2u(Q1i[k0] * TEMP_INV, Q1i[k0 + 1] * TEMP_INV);
            qb[ktp][2] = h2u(Q0i[k1] * TEMP_INV, Q0i[k1 + 1] * TEMP_INV);
            qb[ktp][3] = h2u(Q1i[k1] * TEMP_INV, Q1i[k1 + 1] * TEMP_INV);
        }
    }

    float ore[8][4], oim[8][4];
#pragma unroll
    for (int nt = 0; nt < 8; ++nt)
#pragma unroll
        for (int j = 0; j < 4; ++j) { ore[nt][j] = 0.f; oim[nt][j] = 0.f; }
    float lsum0 = 0.f, lsum1 = 0.f;

    // tile 0 load: K 1024 + V 1024 chunks with 128 threads
#pragma unroll
    for (int j = 0; j < 8; ++j) {
        cp16(smem4 + tid + (j << 7),        srcK + tid + (j << 7));
        cp16(smem4 + 2048 + tid + (j << 7), srcV + tid + (j << 7));
    }
    asm volatile("cp.async.commit_group;" ::: "memory");
    asm volatile("cp.async.wait_group 0;" ::: "memory");
    __syncthreads();

    for (int t = 0; t < NT; ++t) {
        if (t + 1 < NT) {
            const int nb = (t + 1) & 1, tb = (t + 1) << 10;
#pragma unroll
            for (int j = 0; j < 8; ++j) {
                cp16(smem4 + (nb << 10) + tid + (j << 7),        srcK + tb + tid + (j << 7));
                cp16(smem4 + 2048 + (nb << 10) + tid + (j << 7), srcV + tb + tid + (j << 7));
            }
        }
        asm volatile("cp.async.commit_group;" ::: "memory");

        const uint4* kb = smem4 + ((t & 1) << 10);
        const uint4* vb = smem4 + 2048 + ((t & 1) << 10);

        // ---- pair-granular: QK(pair) -> softmax(pair) -> PV-group(pair) ----
#pragma unroll
        for (int p = 0; p < 4; ++p) {
            uint32_t ap[4], ai[4];
#pragma unroll
            for (int h = 0; h < 2; ++h) {
                const int nt = 2 * p + h;
                float sre[4] = {0.f, 0.f, 0.f, 0.f};
                float sim_[4] = {0.f, 0.f, 0.f, 0.f};
#pragma unroll
                for (int ktp = 0; ktp < 4; ++ktp) {
                    uint4 f = kb[(((nt << 2) + ktp) << 5) + lane];
                    mma16(sre,  qa[ktp], f.x, f.y);
                    mma16(sim_, qa[ktp], f.z, f.w);
                    mma16(sre,  qb[ktp], f.z ^ SGNH, f.w ^ SGNH);
                    mma16(sim_, qb[ktp], f.x, f.y);
                }
                float pr[4], pi[4];
#pragma unroll
                for (int j = 0; j < 4; ++j) {
                    float x = sre[j], y = sim_[j];
                    float r2 = fmaf(x, x, y * y);
                    float ri = rsqrtf(fmaxf(r2, 1e-24f));
                    float e  = __expf(r2 * ri);
                    float wt = e * ri;
                    pr[j] = x * wt;
                    pi[j] = y * wt;
                    if (j < 2) lsum0 += e; else lsum1 += e;
                }
                ap[2 * h]     = h2u(pr[0], pr[1]);
                ap[2 * h + 1] = h2u(pr[2], pr[3]);
                ai[2 * h]     = h2u(pi[0], pi[1]);
                ai[2 * h + 1] = h2u(pi[2], pi[3]);
            }
            uint32_t ain[4] = {ai[0] ^ SGNH, ai[1] ^ SGNH, ai[2] ^ SGNH, ai[3] ^ SGNH};
#pragma unroll
            for (int nt = 0; nt < 8; ++nt) {
                uint4 v = vb[(((nt << 2) + p) << 5) + lane];
                mma16(ore[nt], ap,  v.x, v.y);
                mma16(oim[nt], ap,  v.z, v.w);
                mma16(ore[nt], ain, v.z, v.w);
                mma16(oim[nt], ai,  v.x, v.y);
            }
        }

        asm volatile("cp.async.wait_group 0;" ::: "memory");
        __syncthreads();
    }

    // ---- epilogue ----
    lsum0 += __shfl_xor_sync(0xffffffffu, lsum0, 1);
    lsum0 += __shfl_xor_sync(0xffffffffu, lsum0, 2);
    lsum1 += __shfl_xor_sync(0xffffffffu, lsum1, 1);
    lsum1 += __shfl_xor_sync(0xffffffffu, lsum1, 2);
    const float inv0 = 1.0f / lsum0;
    const float inv1 = 1.0f / lsum1;

    float* OutR = out + hoff;
    float* OutI = out + (size_t)PLANE + hoff;
    const int r0 = (m0 + w * 16 + g) * 64;
    const int r1 = r0 + 8 * 64;
#pragma unroll
    for (int nt = 0; nt < 8; ++nt) {
        int c = nt * 8 + 2 * l;
        *(float2*)(OutR + r0 + c) = make_float2(ore[nt][0] * inv0, ore[nt][1] * inv0);
        *(float2*)(OutI + r0 + c) = make_float2(oim[nt][0] * inv0, oim[nt][1] * inv0);
        *(float2*)(OutR + r1 + c) = make_float2(ore[nt][2] * inv1, ore[nt][3] * inv1);
        *(float2*)(OutI + r1 + c) = make_float2(oim[nt][2] * inv1, oim[nt][3] * inv1);
    }
}

extern "C" void kernel_launch(void* const* d_in, const int* in_sizes, int n_in,
                              void* d_out, int out_size)
{
    (void)in_sizes; (void)n_in; (void)out_size;
    prep_k<<<4096, 256>>>((const float*)d_in[2], (const float*)d_in[3]);
    prep_v<<<4096, 256>>>((const float*)d_in[4], (const float*)d_in[5]);

    cudaFuncSetAttribute(cvattn_mma, cudaFuncAttributeMaxDynamicSharedMemorySize, SMEM_BYTES);
    dim3 grid(SLEN / 64, 32);
    cvattn_mma<<<grid, 128, SMEM_BYTES>>>(
        (const float*)d_in[0], (const float*)d_in[1], (float*)d_out);
}